// round 14
// baseline (speedup 1.0000x reference)
#include <cuda_runtime.h>
#include <cuda_bf16.h>
#include <cstdint>
#include <cstddef>

// B=4, N=256, E=512. Persistent kernel: 296 CTAs (2/SM forced) x 128 threads.
// Static schedule, grid barriers between phases:
//   P1: G = tril( X X^T )        (32x64 lower tiles, K=512, 80 jobs)
//   P2: S = tril( G Kw )         (80 jobs, K = (r+1)*32; G pre-masked)
//   P3: T = tril( S Qw^T )       (80 jobs)
//   P4: F = T X                  (256 jobs, fp32)
//   P5: out = x*(1 + f - x.f)    (1024 jobs)
// Masks applied at STORE time only (G/S/T stored tril-masked), so every
// consumer GEMM is unmasked. Engine: mma.sync m16n8k8 tf32, 2-way split
// (D += Ah*Bh + Ah*Bl + Al*Bh), fp32 accum (err ~2^-22).
// Staging: cp.async.cg, 4 stages in flight, 5 smem slots -> L2 latency
// fully hidden by compute. Deterministic static schedule.

#define NN_  256
#define EE_  512
#define GRID 296
#define PIPE  4
#define SLOTS 5

__device__ __align__(16) float g_G[4 * NN_ * NN_];
__device__ __align__(16) float g_S[4 * NN_ * NN_];
__device__ __align__(16) float g_T[4 * NN_ * NN_];
__device__ __align__(16) float g_F[4 * NN_ * EE_];

__device__ __align__(128) unsigned bar_cnt[64];
__device__ __align__(128) unsigned bar_gen[64];

__device__ __forceinline__ void grid_barrier(int idx) {
    __syncthreads();
    if (threadIdx.x == 0) {
        volatile unsigned* genp = &bar_gen[idx * 8];
        const unsigned g = *genp;
        __threadfence();
        if (atomicAdd(&bar_cnt[idx * 8], 1u) == GRID - 1) {
            bar_cnt[idx * 8] = 0;
            __threadfence();
            atomicAdd(&bar_gen[idx * 8], 1u);
        } else {
            while (*genp == g) { }
        }
        __threadfence();
    }
    __syncthreads();
}

__device__ __forceinline__ unsigned f2tf(float x) {
    unsigned r;
    asm("cvt.rna.tf32.f32 %0, %1;" : "=r"(r) : "f"(x));
    return r;
}
__device__ __forceinline__ void mma_tf32(float* c, const unsigned* a,
                                         unsigned b0, unsigned b1) {
    asm("mma.sync.aligned.m16n8k8.row.col.f32.tf32.tf32.f32 "
        "{%0,%1,%2,%3},{%4,%5,%6,%7},{%8,%9},{%0,%1,%2,%3};"
        : "+f"(c[0]), "+f"(c[1]), "+f"(c[2]), "+f"(c[3])
        : "r"(a[0]), "r"(a[1]), "r"(a[2]), "r"(a[3]), "r"(b0), "r"(b1));
}

__device__ __forceinline__ void cp16(void* sdst, const void* gsrc) {
    const unsigned d = (unsigned)__cvta_generic_to_shared(sdst);
    asm volatile("cp.async.cg.shared.global [%0], [%1], 16;"
                 :: "r"(d), "l"(gsrc));
}
#define CP_COMMIT() asm volatile("cp.async.commit_group;")
#define CP_WAIT3()  asm volatile("cp.async.wait_group 3;")

// One 32(M) x 64(N) output tile, k = [0, nst*16).
// A row-major [i][k] (lda). NT: B[j][k] row-major (ldb), else B[k][j].
// MASK_C: zero C[i][j] for j > i at store. C fp32 (ldc).
// 4 warps: wm = warp&1 (16-row half), wn = warp>>1 (32-col half);
// per warp 1 m16 x 4 n8 mma tiles, tf32 2-way split (3 mma each).
// cp.async pipeline: PIPE=4 in flight, SLOTS=5 smem slots.
template<bool NT, bool MASK_C>
__device__ __forceinline__ void tile_gemm(
    const float* __restrict__ A, int lda,
    const float* __restrict__ B, int ldb,
    float* __restrict__ C, int ldc,
    int i0, int j0, int nst,
    float (*As)[32 * 20], float (*Bs)[1280])
{
    const int tid  = threadIdx.x;
    const int lane = tid & 31;
    const int warp = tid >> 5;
    const int wm   = warp & 1;
    const int wn   = warp >> 1;
    const int g    = lane >> 2;
    const int t    = lane & 3;

    const int arow = tid >> 2;            // 0..31
    const int ac4  = (tid & 3) << 2;      // 0,4,8,12

    auto issue_stage = [&](int s) {
        const int kg   = s * 16;
        const int slot = s % SLOTS;
        cp16(&As[slot][arow * 20 + ac4],
             &A[(size_t)(i0 + arow) * lda + kg + ac4]);
        #pragma unroll
        for (int h = 0; h < 2; h++) {
            const int c = tid + h * 128;
            if (NT) {
                const int row = c >> 2, cc = (c & 3) << 2;     // 64 x 16
                cp16(&Bs[slot][row * 20 + cc],
                     &B[(size_t)(j0 + row) * ldb + kg + cc]);
            } else {
                const int row = c >> 4, cc = (c & 15) << 2;    // 16 x 64
                cp16(&Bs[slot][row * 72 + cc],
                     &B[(size_t)(kg + row) * ldb + j0 + cc]);
            }
        }
    };

    float acc[4][4] = {};

    #pragma unroll
    for (int s = 0; s < PIPE; s++) {
        if (s < nst) issue_stage(s);
        CP_COMMIT();
    }

    #pragma unroll 1
    for (int s = 0; s < nst; s++) {
        CP_WAIT3();
        __syncthreads();
        if (s + PIPE < nst) issue_stage(s + PIPE);   // slot (s+4)%5 == (s-1)%5: free
        CP_COMMIT();

        const float* Asl = As[s % SLOTS];
        const float* Bsl = Bs[s % SLOTS];
        #pragma unroll
        for (int kk = 0; kk < 16; kk += 8) {
            unsigned ahi[4], alo[4];
            #pragma unroll
            for (int r = 0; r < 4; r++) {
                const int row = wm * 16 + g + ((r & 1) << 3);
                const int kc  = kk + t + ((r >> 1) << 2);
                const float v = Asl[row * 20 + kc];
                const unsigned hb = f2tf(v);
                ahi[r] = hb;
                alo[r] = f2tf(v - __uint_as_float(hb));
            }
            #pragma unroll
            for (int u = 0; u < 4; u++) {
                const int col = wn * 32 + u * 8 + g;
                const float v0 = NT ? Bsl[col * 20 + kk + t]
                                    : Bsl[(kk + t) * 72 + col];
                const float v1 = NT ? Bsl[col * 20 + kk + t + 4]
                                    : Bsl[(kk + t + 4) * 72 + col];
                const unsigned bh0 = f2tf(v0), bh1 = f2tf(v1);
                const unsigned bl0 = f2tf(v0 - __uint_as_float(bh0));
                const unsigned bl1 = f2tf(v1 - __uint_as_float(bh1));
                mma_tf32(acc[u], ahi, bh0, bh1);
                mma_tf32(acc[u], ahi, bl0, bl1);
                mma_tf32(acc[u], alo, bh0, bh1);
            }
        }
    }

    #pragma unroll
    for (int u = 0; u < 4; u++) {
        const int jb = j0 + wn * 32 + u * 8 + 2 * t;
        #pragma unroll
        for (int h = 0; h < 2; h++) {
            const int i = i0 + wm * 16 + g + h * 8;
            float c0 = acc[u][2 * h], c1 = acc[u][2 * h + 1];
            if (MASK_C) {
                if (jb > i)     c0 = 0.f;
                if (jb + 1 > i) c1 = 0.f;
            }
            *(float2*)&C[(size_t)i * ldc + jb] = make_float2(c0, c1);
        }
    }
    __syncthreads();   // protect smem slots before next job's prologue
}

// 20 lower 32x64 tiles per 256x256 (r 0..7; c*64 <= r*32+31)
__constant__ int t20_r[20] = {0,1,2,2,3,3,4,4,4,5,5,5,6,6,6,6,7,7,7,7};
__constant__ int t20_c[20] = {0,0,0,1,0,1,0,1,2,0,1,2,0,1,2,3,0,1,2,3};

__global__ __launch_bounds__(128, 2)
void replicator_async(const float* __restrict__ X,
                      const float* __restrict__ Qw,
                      const float* __restrict__ Kw,
                      float* __restrict__ out)
{
    __shared__ float As[SLOTS][32 * 20];   // 12.8 KB
    __shared__ float Bs[SLOTS][1280];      // 25.6 KB
    __shared__ float red[4];

    const int tid = threadIdx.x;
    const size_t sX = (size_t)NN_ * EE_;
    const size_t sG = (size_t)NN_ * NN_;

    // ---- P1: G = tril(X X^T), 80 jobs, K=512 (32 stages)
    for (int job = blockIdx.x; job < 80; job += GRID) {
        const int b = job / 20;
        const int e = job - b * 20;
        tile_gemm<true, true>(
            X + b * sX, EE_, X + b * sX, EE_, g_G + b * sG, NN_,
            t20_r[e] * 32, t20_c[e] * 64, 32, As, Bs);
    }
    grid_barrier(0);

    // ---- P2: S = tril(G Kw), 80 jobs, nst = 2r+2 (G pre-masked)
    for (int job = blockIdx.x; job < 80; job += GRID) {
        const int b = job / 20;
        const int e = job - b * 20;
        tile_gemm<false, true>(
            g_G + b * sG, NN_, Kw, NN_, g_S + b * sG, NN_,
            t20_r[e] * 32, t20_c[e] * 64, 2 * t20_r[e] + 2, As, Bs);
    }
    grid_barrier(1);

    // ---- P3: T = tril(S Qw^T), 80 jobs
    for (int job = blockIdx.x; job < 80; job += GRID) {
        const int b = job / 20;
        const int e = job - b * 20;
        tile_gemm<true, true>(
            g_S + b * sG, NN_, Qw, NN_, g_T + b * sG, NN_,
            t20_r[e] * 32, t20_c[e] * 64, 2 * t20_r[e] + 2, As, Bs);
    }
    grid_barrier(2);

    // ---- P4: F = T X, 256 jobs (8 row-bands x 8 e-tiles x 4 batch)
    for (int job = blockIdx.x; job < 256; job += GRID) {
        const int b  = job / 64;
        const int rm = job - b * 64;
        const int r  = rm >> 3;
        const int et = rm & 7;
        tile_gemm<false, false>(
            g_T + b * sG, NN_, X + b * sX, EE_, g_F + b * sX, EE_,
            r * 32, et * 64, 2 * r + 2, As, Bs);
    }
    grid_barrier(3);

    // ---- P5: epilogue, 1024 rows
    for (int job = blockIdx.x; job < 1024; job += GRID) {
        const size_t base = (size_t)job * EE_;

        float4 x = *(const float4*)&X[base + tid * 4];
        float4 f = *(const float4*)&g_F[base + tid * 4];

        float sum = x.x * f.x + x.y * f.y + x.z * f.z + x.w * f.w;
        #pragma unroll
        for (int o = 16; o; o >>= 1)
            sum += __shfl_xor_sync(0xffffffffu, sum, o);

        if ((tid & 31) == 0) red[tid >> 5] = sum;
        __syncthreads();
        const float avg = red[0] + red[1] + red[2] + red[3];

        float4 o;
        o.x = x.x * (1.f + f.x - avg);
        o.y = x.y * (1.f + f.y - avg);
        o.z = x.z * (1.f + f.z - avg);
        o.w = x.w * (1.f + f.w - avg);
        *(float4*)&out[base + tid * 4] = o;
        __syncthreads();
    }
}

extern "C" void kernel_launch(void* const* d_in, const int* in_sizes, int n_in,
                              void* d_out, int out_size)
{
    const float* X  = (const float*)d_in[0];   // (4,256,512)
    const float* Qw = (const float*)d_in[1];   // (256,256)
    const float* Kw = (const float*)d_in[2];   // (256,256)
    float* out = (float*)d_out;                // (4,256,512)

    replicator_async<<<GRID, 128>>>(X, Qw, Kw, out);
}

// round 15
// speedup vs baseline: 1.1611x; 1.1611x over previous
#include <cuda_runtime.h>
#include <cstdint>
#include <cstddef>

// B=4, N=256, E=512. Persistent kernel: 296 CTAs x 128 threads. Phases:
//   P1: G(2 k-part planes) = X X^T   (32x64 lower tiles, k32 stages, 160 jobs)
//   P2: S = tril( (G0+G1) Kw )       (80 jobs, nst = r+1)
//   P3: T = tril( S Qw^T )           (80 jobs)
//   P4: F = T X                      (256 jobs)
//   P5: out = x*(1 + f - x.f)        (1024 jobs)
// tril masks applied at STORE only, so consumer GEMMs are unmasked; tiles
// never written stay .bss zero. Engine: mma.sync m16n8k16 bf16 with 2-way
// split operands (D += Ah*Bh + Al*Bh + Ah*Bl), fp32 accum; hi/lo produced
// with packed cvt.rn.bf16x2 + LOP/ADD only (no slow F2F). Staging: B via
// cp.async (3 slots, 2 stages in flight), A via register prefetch (allows
// the 2-plane G sum). Deterministic static schedule, no data-path atomics.

#define NN_  256
#define EE_  512
#define GRID 296
#define GPLANE (4 * NN_ * NN_)

typedef unsigned u32;

__device__ __align__(16) float g_G[2 * GPLANE];
__device__ __align__(16) float g_S[GPLANE];
__device__ __align__(16) float g_T[GPLANE];
__device__ __align__(16) float g_F[4 * NN_ * EE_];

__device__ __align__(128) unsigned bar_cnt[64];
__device__ __align__(128) unsigned bar_gen[64];

__device__ __forceinline__ void grid_barrier(int idx) {
    __syncthreads();
    if (threadIdx.x == 0) {
        volatile unsigned* genp = &bar_gen[idx * 8];
        const unsigned g = *genp;
        __threadfence();
        if (atomicAdd(&bar_cnt[idx * 8], 1u) == GRID - 1) {
            bar_cnt[idx * 8] = 0;
            __threadfence();
            atomicAdd(&bar_gen[idx * 8], 1u);
        } else {
            while (*genp == g) { }
        }
        __threadfence();
    }
    __syncthreads();
}

// Split (v0, v1) into packed bf16 hi pair and bf16 lo pair (v ~ hi + lo).
// d.lo16 = first element. Pure fma/alu ops, no F2F.
__device__ __forceinline__ void split2(float v0, float v1, u32& h, u32& l) {
    asm("cvt.rn.bf16x2.f32 %0, %1, %2;" : "=r"(h) : "f"(v1), "f"(v0));
    const float h0 = __uint_as_float(h << 16);
    const float h1 = __uint_as_float(h & 0xFFFF0000u);
    const float l0 = v0 - h0;
    const float l1 = v1 - h1;
    asm("cvt.rn.bf16x2.f32 %0, %1, %2;" : "=r"(l) : "f"(l1), "f"(l0));
}

__device__ __forceinline__ void mma_bf16(float* c, const u32* a, u32 b0, u32 b1) {
    asm("mma.sync.aligned.m16n8k16.row.col.f32.bf16.bf16.f32 "
        "{%0,%1,%2,%3},{%4,%5,%6,%7},{%8,%9},{%0,%1,%2,%3};"
        : "+f"(c[0]), "+f"(c[1]), "+f"(c[2]), "+f"(c[3])
        : "r"(a[0]), "r"(a[1]), "r"(a[2]), "r"(a[3]), "r"(b0), "r"(b1));
}

__device__ __forceinline__ void cp16(void* sdst, const void* gsrc) {
    const u32 d = (u32)__cvta_generic_to_shared(sdst);
    asm volatile("cp.async.cg.shared.global [%0], [%1], 16;" :: "r"(d), "l"(gsrc));
}
#define CP_COMMIT() asm volatile("cp.async.commit_group;")
#define CP_WAIT1()  asm volatile("cp.async.wait_group 1;")

// One 32(M) x 64(N) tile, k in [kbase, kbase + nst*32), stages of k=32.
// A row-major [i][k] (lda), summed over ASUM planes (stride aStride).
// NT: B[j][k] row-major (ldb); else B[k][j]. MASK_C: tril mask at store.
// 4 warps: wm = warp&1 (m16 half), wn = warp>>1 (n32 half; 4 n8 tiles).
template<bool NT, bool MASK_C, int ASUM>
__device__ __forceinline__ void tile_gemm(
    const float* __restrict__ A, int lda, size_t aStride,
    const float* __restrict__ B, int ldb,
    float* __restrict__ C, int ldc,
    int i0, int j0, int kbase, int nst,
    float (*As)[1152],     // [2][32 rows][36]
    float (*Bs)[2304])     // [3]; NT: [64 cols][36], NN: [32 k][72]
{
    const int tid  = threadIdx.x;
    const int lane = tid & 31;
    const int warp = tid >> 5;
    const int wm   = warp & 1;
    const int wn   = warp >> 1;
    const int g    = lane >> 2;
    const int t    = lane & 3;

    const int arow = tid >> 2;          // 0..31
    const int ac8  = (tid & 3) << 3;    // 0,8,16,24

    float4 rA[2];

    auto loadA = [&](int s) {
        const int kg = kbase + s * 32;
        #pragma unroll
        for (int it = 0; it < 2; it++) {
            const size_t off = (size_t)(i0 + arow) * lda + kg + ac8 + it * 4;
            float4 v = *(const float4*)&A[off];
            if (ASUM == 2) {
                const float4 w = *(const float4*)&A[off + aStride];
                v.x += w.x; v.y += w.y; v.z += w.z; v.w += w.w;
            }
            rA[it] = v;
        }
    };
    auto stsA = [&](int s) {
        float* dst = &As[s & 1][arow * 36 + ac8];
        *(float4*)&dst[0] = rA[0];
        *(float4*)&dst[4] = rA[1];
    };
    auto issueB = [&](int s) {
        const int kg   = kbase + s * 32;
        float* slot = Bs[s % 3];
        #pragma unroll
        for (int h = 0; h < 4; h++) {
            const int idx = tid + h * 128;
            if (NT) {
                const int col = idx >> 3, kk = (idx & 7) << 2;
                cp16(&slot[col * 36 + kk],
                     &B[(size_t)(j0 + col) * ldb + kg + kk]);
            } else {
                const int kr = idx >> 4, cc = (idx & 15) << 2;
                cp16(&slot[kr * 72 + cc],
                     &B[(size_t)(kg + kr) * ldb + j0 + cc]);
            }
        }
    };

    float acc[4][4] = {};

    auto compute = [&](int s) {
        const float* Asl = As[s & 1];
        const float* Bsl = Bs[s % 3];
        #pragma unroll
        for (int kk = 0; kk < 32; kk += 16) {
            u32 ah[4], al[4];
            const int r0 = wm * 16 + g;
            const float2 a0 = *(const float2*)&Asl[r0 * 36 + kk + 2 * t];
            const float2 a1 = *(const float2*)&Asl[(r0 + 8) * 36 + kk + 2 * t];
            const float2 a2 = *(const float2*)&Asl[r0 * 36 + kk + 2 * t + 8];
            const float2 a3 = *(const float2*)&Asl[(r0 + 8) * 36 + kk + 2 * t + 8];
            split2(a0.x, a0.y, ah[0], al[0]);
            split2(a1.x, a1.y, ah[1], al[1]);
            split2(a2.x, a2.y, ah[2], al[2]);
            split2(a3.x, a3.y, ah[3], al[3]);
            #pragma unroll
            for (int u = 0; u < 4; u++) {
                const int col = wn * 32 + u * 8 + g;
                float2 q0, q1;
                if (NT) {
                    q0 = *(const float2*)&Bsl[col * 36 + kk + 2 * t];
                    q1 = *(const float2*)&Bsl[col * 36 + kk + 2 * t + 8];
                } else {
                    q0.x = Bsl[(kk + 2 * t) * 72 + col];
                    q0.y = Bsl[(kk + 2 * t + 1) * 72 + col];
                    q1.x = Bsl[(kk + 2 * t + 8) * 72 + col];
                    q1.y = Bsl[(kk + 2 * t + 9) * 72 + col];
                }
                u32 bh0, bl0, bh1, bl1;
                split2(q0.x, q0.y, bh0, bl0);
                split2(q1.x, q1.y, bh1, bl1);
                mma_bf16(acc[u], ah, bh0, bh1);
                mma_bf16(acc[u], al, bh0, bh1);
                mma_bf16(acc[u], ah, bl0, bl1);
            }
        }
    };

    // prologue: A0 staged; B0, B1 in flight; A1 in regs
    loadA(0);
    stsA(0);
    issueB(0);
    CP_COMMIT();
    if (nst > 1) issueB(1);
    CP_COMMIT();
    if (nst > 1) loadA(1);

    #pragma unroll 1
    for (int s = 0; s < nst; s++) {
        CP_WAIT1();            // B_s landed (newest group may be pending)
        __syncthreads();       // visibility + all warps done compute(s-1)
        if (s + 1 < nst) stsA(s + 1);
        if (s + 2 < nst) { loadA(s + 2); issueB(s + 2); }
        CP_COMMIT();
        compute(s);
    }

    #pragma unroll
    for (int u = 0; u < 4; u++) {
        const int jb = j0 + wn * 32 + u * 8 + 2 * t;
        #pragma unroll
        for (int h = 0; h < 2; h++) {
            const int i = i0 + wm * 16 + g + h * 8;
            float c0 = acc[u][2 * h], c1 = acc[u][2 * h + 1];
            if (MASK_C) {
                if (jb > i)     c0 = 0.f;
                if (jb + 1 > i) c1 = 0.f;
            }
            *(float2*)&C[(size_t)i * ldc + jb] = make_float2(c0, c1);
        }
    }
    __syncthreads();   // smem safe for next job
}

// 20 lower 32x64 tiles per 256x256 (band r 0..7; c*64 <= r*32+31)
__constant__ int t20_r[20] = {0,1,2,2,3,3,4,4,4,5,5,5,6,6,6,6,7,7,7,7};
__constant__ int t20_c[20] = {0,0,0,1,0,1,0,1,2,0,1,2,0,1,2,3,0,1,2,3};

__global__ __launch_bounds__(128)
void replicator_bsplit(const float* __restrict__ X,
                       const float* __restrict__ Qw,
                       const float* __restrict__ Kw,
                       float* __restrict__ out)
{
    __shared__ float As[2][1152];   //  9.2 KB
    __shared__ float Bs[3][2304];   // 27.6 KB
    __shared__ float red[4];

    const int tid = threadIdx.x;
    const size_t sX = (size_t)NN_ * EE_;
    const size_t sG = (size_t)NN_ * NN_;

    // ---- P1: G planes = X X^T, 160 jobs (b x 20 tiles x 2 k-parts), nst=8
    for (int job = blockIdx.x; job < 160; job += GRID) {
        const int b  = job / 40;
        const int rm = job - b * 40;
        const int e  = rm >> 1;
        const int kp = rm & 1;
        tile_gemm<true, true, 1>(
            X + b * sX, EE_, 0, X + b * sX, EE_,
            g_G + (size_t)kp * GPLANE + b * sG, NN_,
            t20_r[e] * 32, t20_c[e] * 64, kp * 256, 8, As, Bs);
    }
    grid_barrier(0);

    // ---- P2: S = tril( (G0+G1) Kw ), 80 jobs, nst = r+1
    for (int job = blockIdx.x; job < 80; job += GRID) {
        const int b = job / 20;
        const int e = job - b * 20;
        tile_gemm<false, true, 2>(
            g_G + b * sG, NN_, (size_t)GPLANE, Kw, NN_,
            g_S + b * sG, NN_,
            t20_r[e] * 32, t20_c[e] * 64, 0, t20_r[e] + 1, As, Bs);
    }
    grid_barrier(1);

    // ---- P3: T = tril( S Qw^T ), 80 jobs
    for (int job = blockIdx.x; job < 80; job += GRID) {
        const int b = job / 20;
        const int e = job - b * 20;
        tile_gemm<true, true, 1>(
            g_S + b * sG, NN_, 0, Qw, NN_,
            g_T + b * sG, NN_,
            t20_r[e] * 32, t20_c[e] * 64, 0, t20_r[e] + 1, As, Bs);
    }
    grid_barrier(2);

    // ---- P4: F = T X, 256 jobs (b x 8 bands x 8 e-tiles), nst = r+1
    for (int job = blockIdx.x; job < 256; job += GRID) {
        const int b  = job / 64;
        const int rm = job - b * 64;
        const int r  = rm >> 3;
        const int et = rm & 7;
        tile_gemm<false, false, 1>(
            g_T + b * sG, NN_, 0, X + b * sX, EE_,
            g_F + b * sX, EE_,
            r * 32, et * 64, 0, r + 1, As, Bs);
    }
    grid_barrier(3);

    // ---- P5: epilogue, 1024 rows
    for (int job = blockIdx.x; job < 1024; job += GRID) {
        const size_t base = (size_t)job * EE_;

        float4 x = *(const float4*)&X[base + tid * 4];
        float4 f = *(const float4*)&g_F[base + tid * 4];

        float sum = x.x * f.x + x.y * f.y + x.z * f.z + x.w * f.w;
        #pragma unroll
        for (int o = 16; o; o >>= 1)
            sum += __shfl_xor_sync(0xffffffffu, sum, o);

        if ((tid & 31) == 0) red[tid >> 5] = sum;
        __syncthreads();
        const float avg = red[0] + red[1] + red[2] + red[3];

        float4 o;
        o.x = x.x * (1.f + f.x - avg);
        o.y = x.y * (1.f + f.y - avg);
        o.z = x.z * (1.f + f.z - avg);
        o.w = x.w * (1.f + f.w - avg);
        *(float4*)&out[base + tid * 4] = o;
        __syncthreads();
    }
}

extern "C" void kernel_launch(void* const* d_in, const int* in_sizes, int n_in,
                              void* d_out, int out_size)
{
    const float* X  = (const float*)d_in[0];   // (4,256,512)
    const float* Qw = (const float*)d_in[1];   // (256,256)
    const float* Kw = (const float*)d_in[2];   // (256,256)
    float* out = (float*)d_out;                // (4,256,512)

    replicator_bsplit<<<GRID, 128>>>(X, Qw, Kw, out);
}

// round 16
// speedup vs baseline: 1.4374x; 1.2380x over previous
#include <cuda_runtime.h>
#include <cstdint>
#include <cstddef>

// B=4, N=256, E=512. Persistent kernel: 592 CTAs (4/SM, forced by
// __launch_bounds__(128,4)) x 128 threads. Static schedule, grid barriers:
//   P1: G(4 k-planes) = X X^T        (32x64 lower tiles, nst=4, 320 jobs)
//   P2: S(2 planes) = tril((sum4 G) Kw)   (136 jobs, nst<=4)
//   P3: T(2 planes) = tril((sum2 S) Qw^T) (136 jobs, nst<=4)
//   P4: F(2 planes) = (sum2 T) X          (384 jobs, nst<=4)
//   P5: out = x*(1 + f - x.f), f = F0+F1  (1024 jobs)
// tril masks applied at STORE only; plane tiles never written stay .bss
// zero, so plane-sums read exact zeros. Engine: mma.sync m16n8k16 bf16,
// 2-way split operands (D += Ah*Bh + Al*Bh + Ah*Bl) with split
// accumulators (short mma chains), fp32 accum; hi/lo via packed
// cvt.rn.bf16x2 + ALU only. B staged via cp.async (3 slots, 2 ahead),
// A via register prefetch (supports plane sums). Deterministic.

#define NN_  256
#define EE_  512
#define GRID 592
#define GPLANE (4 * NN_ * NN_)
#define FPLANE (4 * NN_ * EE_)

typedef unsigned u32;

__device__ __align__(16) float g_G[4 * GPLANE];
__device__ __align__(16) float g_S[2 * GPLANE];
__device__ __align__(16) float g_T[2 * GPLANE];
__device__ __align__(16) float g_F[2 * FPLANE];

__device__ __align__(128) unsigned bar_cnt[64];
__device__ __align__(128) unsigned bar_gen[64];

__device__ __forceinline__ void grid_barrier(int idx) {
    __syncthreads();
    if (threadIdx.x == 0) {
        volatile unsigned* genp = &bar_gen[idx * 8];
        const unsigned g = *genp;
        __threadfence();
        if (atomicAdd(&bar_cnt[idx * 8], 1u) == GRID - 1) {
            bar_cnt[idx * 8] = 0;
            __threadfence();
            atomicAdd(&bar_gen[idx * 8], 1u);
        } else {
            while (*genp == g) { }
        }
        __threadfence();
    }
    __syncthreads();
}

// Split (v0, v1) -> packed bf16 hi pair + bf16 lo pair (v ~ hi + lo).
__device__ __forceinline__ void split2(float v0, float v1, u32& h, u32& l) {
    asm("cvt.rn.bf16x2.f32 %0, %1, %2;" : "=r"(h) : "f"(v1), "f"(v0));
    const float h0 = __uint_as_float(h << 16);
    const float h1 = __uint_as_float(h & 0xFFFF0000u);
    const float l0 = v0 - h0;
    const float l1 = v1 - h1;
    asm("cvt.rn.bf16x2.f32 %0, %1, %2;" : "=r"(l) : "f"(l1), "f"(l0));
}

__device__ __forceinline__ void mma_bf16(float* c, const u32* a, u32 b0, u32 b1) {
    asm("mma.sync.aligned.m16n8k16.row.col.f32.bf16.bf16.f32 "
        "{%0,%1,%2,%3},{%4,%5,%6,%7},{%8,%9},{%0,%1,%2,%3};"
        : "+f"(c[0]), "+f"(c[1]), "+f"(c[2]), "+f"(c[3])
        : "r"(a[0]), "r"(a[1]), "r"(a[2]), "r"(a[3]), "r"(b0), "r"(b1));
}

__device__ __forceinline__ void cp16(void* sdst, const void* gsrc) {
    const u32 d = (u32)__cvta_generic_to_shared(sdst);
    asm volatile("cp.async.cg.shared.global [%0], [%1], 16;" :: "r"(d), "l"(gsrc));
}
#define CP_COMMIT() asm volatile("cp.async.commit_group;")
#define CP_WAIT1()  asm volatile("cp.async.wait_group 1;")

// One 32(M) x 64(N) tile, k in [kbase, kbase + nst*32), stages of k=32.
// A row-major [i][k] (lda), summed over ASUM part planes (stride aStride).
// NT: B[j][k] row-major (ldb); else B[k][j]. MASK_C: tril mask at store.
// 4 warps: wm = warp&1 (m16 half), wn = warp>>1 (n32 half; 4 n8 tiles).
template<bool NT, bool MASK_C, int ASUM>
__device__ __forceinline__ void tile_gemm(
    const float* __restrict__ A, int lda, size_t aStride,
    const float* __restrict__ B, int ldb,
    float* __restrict__ C, int ldc,
    int i0, int j0, int kbase, int nst,
    float (*As)[1152],     // [2][32 rows][36]
    float (*Bs)[2304])     // [3]; NT: [64 cols][36], NN: [32 k][72]
{
    const int tid  = threadIdx.x;
    const int lane = tid & 31;
    const int warp = tid >> 5;
    const int wm   = warp & 1;
    const int wn   = warp >> 1;
    const int g    = lane >> 2;
    const int t    = lane & 3;

    const int arow = tid >> 2;          // 0..31
    const int ac8  = (tid & 3) << 3;    // 0,8,16,24

    float4 rA[2];

    auto loadA = [&](int s) {
        const int kg = kbase + s * 32;
        #pragma unroll
        for (int it = 0; it < 2; it++) {
            const size_t off = (size_t)(i0 + arow) * lda + kg + ac8 + it * 4;
            float4 v = *(const float4*)&A[off];
            #pragma unroll
            for (int p = 1; p < ASUM; p++) {
                const float4 w = *(const float4*)&A[off + (size_t)p * aStride];
                v.x += w.x; v.y += w.y; v.z += w.z; v.w += w.w;
            }
            rA[it] = v;
        }
    };
    auto stsA = [&](int s) {
        float* dst = &As[s & 1][arow * 36 + ac8];
        *(float4*)&dst[0] = rA[0];
        *(float4*)&dst[4] = rA[1];
    };
    auto issueB = [&](int s) {
        const int kg = kbase + s * 32;
        float* slot = Bs[s % 3];
        #pragma unroll
        for (int h = 0; h < 4; h++) {
            const int idx = tid + h * 128;
            if (NT) {
                const int col = idx >> 3, kk = (idx & 7) << 2;
                cp16(&slot[col * 36 + kk],
                     &B[(size_t)(j0 + col) * ldb + kg + kk]);
            } else {
                const int kr = idx >> 4, cc = (idx & 15) << 2;
                cp16(&slot[kr * 72 + cc],
                     &B[(size_t)(kg + kr) * ldb + j0 + cc]);
            }
        }
    };

    float accP[4][4] = {};   // hi*hi + hi*lo
    float accQ[4][4] = {};   // lo*hi

    auto compute = [&](int s) {
        const float* Asl = As[s & 1];
        const float* Bsl = Bs[s % 3];
        #pragma unroll
        for (int kk = 0; kk < 32; kk += 16) {
            u32 ah[4], al[4];
            const int r0 = wm * 16 + g;
            const float2 a0 = *(const float2*)&Asl[r0 * 36 + kk + 2 * t];
            const float2 a1 = *(const float2*)&Asl[(r0 + 8) * 36 + kk + 2 * t];
            const float2 a2 = *(const float2*)&Asl[r0 * 36 + kk + 2 * t + 8];
            const float2 a3 = *(const float2*)&Asl[(r0 + 8) * 36 + kk + 2 * t + 8];
            split2(a0.x, a0.y, ah[0], al[0]);
            split2(a1.x, a1.y, ah[1], al[1]);
            split2(a2.x, a2.y, ah[2], al[2]);
            split2(a3.x, a3.y, ah[3], al[3]);
            #pragma unroll
            for (int u = 0; u < 4; u++) {
                const int col = wn * 32 + u * 8 + g;
                float2 q0, q1;
                if (NT) {
                    q0 = *(const float2*)&Bsl[col * 36 + kk + 2 * t];
                    q1 = *(const float2*)&Bsl[col * 36 + kk + 2 * t + 8];
                } else {
                    q0.x = Bsl[(kk + 2 * t) * 72 + col];
                    q0.y = Bsl[(kk + 2 * t + 1) * 72 + col];
                    q1.x = Bsl[(kk + 2 * t + 8) * 72 + col];
                    q1.y = Bsl[(kk + 2 * t + 9) * 72 + col];
                }
                u32 bh0, bl0, bh1, bl1;
                split2(q0.x, q0.y, bh0, bl0);
                split2(q1.x, q1.y, bh1, bl1);
                mma_bf16(accP[u], ah, bh0, bh1);   // hi*hi
                mma_bf16(accQ[u], al, bh0, bh1);   // lo*hi (indep chain)
                mma_bf16(accP[u], ah, bl0, bl1);   // hi*lo
            }
        }
    };

    // prologue: A0 staged; B0, B1 in flight; A1 in regs
    loadA(0);
    stsA(0);
    issueB(0);
    CP_COMMIT();
    if (nst > 1) issueB(1);
    CP_COMMIT();
    if (nst > 1) loadA(1);

    #pragma unroll 1
    for (int s = 0; s < nst; s++) {
        CP_WAIT1();            // B_s landed (newest group may be pending)
        __syncthreads();       // visibility + all warps done with slot reuse
        if (s + 1 < nst) stsA(s + 1);
        if (s + 2 < nst) { loadA(s + 2); issueB(s + 2); }
        CP_COMMIT();
        compute(s);
    }

    #pragma unroll
    for (int u = 0; u < 4; u++) {
        const int jb = j0 + wn * 32 + u * 8 + 2 * t;
        #pragma unroll
        for (int h = 0; h < 2; h++) {
            const int i = i0 + wm * 16 + g + h * 8;
            float c0 = accP[u][2 * h]     + accQ[u][2 * h];
            float c1 = accP[u][2 * h + 1] + accQ[u][2 * h + 1];
            if (MASK_C) {
                if (jb > i)     c0 = 0.f;
                if (jb + 1 > i) c1 = 0.f;
            }
            *(float2*)&C[(size_t)i * ldc + jb] = make_float2(c0, c1);
        }
    }
    __syncthreads();   // smem safe for next job
}

// 20 lower 32x64 tiles per 256x256 (band r 0..7; c*64 <= r*32+31)
__constant__ int t20_r[20] = {0,1,2,2,3,3,4,4,4,5,5,5,6,6,6,6,7,7,7,7};
__constant__ int t20_c[20] = {0,0,0,1,0,1,0,1,2,0,1,2,0,1,2,3,0,1,2,3};
// P2/P3 job table per batch: 34 entries (e, kpart). kpart 1 only for r>=4.
__constant__ int p23_e[34] = {0,1,2,3,4,5,6,7,8,9,10,11,12,13,14,15,16,17,18,19,
                              6,7,8,9,10,11,12,13,14,15,16,17,18,19};
__constant__ int p23_k[34] = {0,0,0,0,0,0,0,0,0,0,0,0,0,0,0,0,0,0,0,0,
                              1,1,1,1,1,1,1,1,1,1,1,1,1,1};

__global__ __launch_bounds__(128, 4)
void replicator_kplane(const float* __restrict__ X,
                       const float* __restrict__ Qw,
                       const float* __restrict__ Kw,
                       float* __restrict__ out)
{
    __shared__ float As[2][1152];   //  9.2 KB
    __shared__ float Bs[3][2304];   // 27.6 KB
    __shared__ float red[4];

    const int tid = threadIdx.x;
    const size_t sX = (size_t)NN_ * EE_;
    const size_t sG = (size_t)NN_ * NN_;

    // ---- P1: G planes(4) = X X^T, 320 jobs (b x 20 tiles x 4 k-parts), nst=4
    for (int job = blockIdx.x; job < 320; job += GRID) {
        const int b  = job / 80;
        const int rm = job - b * 80;
        const int e  = rm >> 2;
        const int kp = rm & 3;
        tile_gemm<true, true, 1>(
            X + b * sX, EE_, 0, X + b * sX, EE_,
            g_G + (size_t)kp * GPLANE + b * sG, NN_,
            t20_r[e] * 32, t20_c[e] * 64, kp * 128, 4, As, Bs);
    }
    grid_barrier(0);

    // ---- P2: S planes(2) = tril( (sum4 G) Kw ), 136 jobs
    for (int job = blockIdx.x; job < 136; job += GRID) {
        const int b  = job / 34;
        const int en = job - b * 34;
        const int e  = p23_e[en];
        const int kp = p23_k[en];
        const int r  = t20_r[e];
        const int nst = kp ? (r - 3) : min(4, r + 1);
        tile_gemm<false, true, 4>(
            g_G + b * sG, NN_, (size_t)GPLANE, Kw, NN_,
            g_S + (size_t)kp * GPLANE + b * sG, NN_,
            r * 32, t20_c[e] * 64, kp * 128, nst, As, Bs);
    }
    grid_barrier(1);

    // ---- P3: T planes(2) = tril( (sum2 S) Qw^T ), 136 jobs
    for (int job = blockIdx.x; job < 136; job += GRID) {
        const int b  = job / 34;
        const int en = job - b * 34;
        const int e  = p23_e[en];
        const int kp = p23_k[en];
        const int r  = t20_r[e];
        const int nst = kp ? (r - 3) : min(4, r + 1);
        tile_gemm<true, true, 2>(
            g_S + b * sG, NN_, (size_t)GPLANE, Qw, NN_,
            g_T + (size_t)kp * GPLANE + b * sG, NN_,
            r * 32, t20_c[e] * 64, kp * 128, nst, As, Bs);
    }
    grid_barrier(2);

    // ---- P4: F planes(2) = (sum2 T) X, 384 jobs (b x 96)
    for (int job = blockIdx.x; job < 384; job += GRID) {
        const int b  = job / 96;
        const int rm = job - b * 96;
        int r, et, kp, nst;
        if (rm < 64) { r = rm >> 3; et = rm & 7; kp = 0; nst = min(4, r + 1); }
        else { const int ix = rm - 64; r = 4 + (ix >> 3); et = ix & 7; kp = 1; nst = r - 3; }
        tile_gemm<false, false, 2>(
            g_T + b * sG, NN_, (size_t)GPLANE, X + b * sX, EE_,
            g_F + (size_t)kp * FPLANE + b * sX, EE_,
            r * 32, et * 64, kp * 128, nst, As, Bs);
    }
    grid_barrier(3);

    // ---- P5: epilogue, 1024 rows (f = F0 + F1)
    for (int job = blockIdx.x; job < 1024; job += GRID) {
        const size_t base = (size_t)job * EE_;

        float4 x  = *(const float4*)&X[base + tid * 4];
        float4 f0 = *(const float4*)&g_F[base + tid * 4];
        float4 f1 = *(const float4*)&g_F[FPLANE + base + tid * 4];
        float4 f  = make_float4(f0.x + f1.x, f0.y + f1.y,
                                f0.z + f1.z, f0.w + f1.w);

        float sum = x.x * f.x + x.y * f.y + x.z * f.z + x.w * f.w;
        #pragma unroll
        for (int o = 16; o; o >>= 1)
            sum += __shfl_xor_sync(0xffffffffu, sum, o);

        if ((tid & 31) == 0) red[tid >> 5] = sum;
        __syncthreads();
        const float avg = red[0] + red[1] + red[2] + red[3];

        float4 o;
        o.x = x.x * (1.f + f.x - avg);
        o.y = x.y * (1.f + f.y - avg);
        o.z = x.z * (1.f + f.z - avg);
        o.w = x.w * (1.f + f.w - avg);
        *(float4*)&out[base + tid * 4] = o;
        __syncthreads();
    }
}

extern "C" void kernel_launch(void* const* d_in, const int* in_sizes, int n_in,
                              void* d_out, int out_size)
{
    const float* X  = (const float*)d_in[0];   // (4,256,512)
    const float* Qw = (const float*)d_in[1];   // (256,256)
    const float* Kw = (const float*)d_in[2];   // (256,256)
    float* out = (float*)d_out;                // (4,256,512)

    replicator_kplane<<<GRID, 128>>>(X, Qw, Kw, out);
}